// round 1
// baseline (speedup 1.0000x reference)
#include <cuda_runtime.h>

#define FULLM 0xFFFFFFFFu
#define NQ 10
#define NL 4

__device__ __forceinline__ float wsum(float v){
  #pragma unroll
  for (int m = 16; m >= 1; m >>= 1) v += __shfl_xor_sync(FULLM, v, m);
  return v;
}

__global__ void __launch_bounds__(256)
hqh_kernel(const float* __restrict__ x,
           const float* __restrict__ params,
           float* __restrict__ out,
           int nTok)
{
  __shared__ float zbs[NQ], xbs[NQ];

  if (threadIdx.x < 32) {
    const int lane = threadIdx.x;
    // state index i = lane*32 + r ; wire q <-> bit (9-q) of i
    // wires 0..4 -> lane bits 4..0 ; wires 5..9 -> register bits 4..0
    float a[32];
    #pragma unroll
    for (int r = 0; r < 32; r++) a[r] = 0.f;
    if (lane == 0) a[0] = 1.f;

    #pragma unroll
    for (int l = 0; l < NL; l++) {
      float th = (lane < NQ) ? params[l * NQ + lane] : 0.f;
      float sv, cv;
      sincosf(0.5f * th, &sv, &cv);

      // --- RY on wires 0..4 (cross-lane butterflies) ---
      #pragma unroll
      for (int q = 0; q < 5; q++) {
        const float c = __shfl_sync(FULLM, cv, q);
        const float s = __shfl_sync(FULLM, sv, q);
        const int m = 1 << (4 - q);
        const bool hi = (lane & m) != 0;
        #pragma unroll
        for (int r = 0; r < 32; r++) {
          float p = __shfl_xor_sync(FULLM, a[r], m);
          // lo: c*a - s*p   hi: s*p + c*a
          a[r] = hi ? fmaf(s, p, c * a[r]) : fmaf(-s, p, c * a[r]);
        }
      }
      // --- RY on wires 5..9 (in-register butterflies) ---
      #pragma unroll
      for (int q = 5; q < 10; q++) {
        const float c = __shfl_sync(FULLM, cv, q);
        const float s = __shfl_sync(FULLM, sv, q);
        const int m = 1 << (9 - q);
        #pragma unroll
        for (int r = 0; r < 32; r++) {
          if ((r & m) == 0) {
            float lo = a[r], hv = a[r | m];
            a[r]     = c * lo - s * hv;
            a[r | m] = fmaf(s, lo, c * hv);
          }
        }
      }
      // --- CNOT(0,1),(1,2),(2,3),(3,4): composed lane permutation ---
      // psi(i) = psi0(g01(g12(g23(g34(i))))); gates applied to src innermost-first
      {
        int src = lane;
        src ^= (src >> 1) & 1;           // g34: b0 ^= b1
        src ^= ((src >> 2) & 1) << 1;    // g23: b1 ^= b2
        src ^= ((src >> 3) & 1) << 2;    // g12: b2 ^= b3
        src ^= ((src >> 4) & 1) << 3;    // g01: b3 ^= b4
        #pragma unroll
        for (int r = 0; r < 32; r++) a[r] = __shfl_sync(FULLM, a[r], src);
      }
      // --- CNOT(4,5): lane bit0 controls swap of register halves (mask 16) ---
      {
        const bool hi = (lane & 1) != 0;
        #pragma unroll
        for (int r = 0; r < 16; r++) {
          float t0 = a[r], t1 = a[r + 16];
          a[r]      = hi ? t1 : t0;
          a[r + 16] = hi ? t0 : t1;
        }
      }
      // --- CNOT(5,6),(6,7),(7,8),(8,9): pure register permutations (free) ---
      #pragma unroll
      for (int q = 5; q < 9; q++) {
        const int mc = 1 << (9 - q);
        const int mt = 1 << (8 - q);
        #pragma unroll
        for (int r = 0; r < 32; r++) {
          if ((r & mc) && !(r & mt)) {
            float t = a[r]; a[r] = a[r | mt]; a[r | mt] = t;
          }
        }
      }
      // --- CNOT(9,0): reg bit0 controls lane-bit4 flip (symmetric exchange) ---
      #pragma unroll
      for (int r = 1; r < 32; r += 2) a[r] = __shfl_xor_sync(FULLM, a[r], 16);
    }

    // --- base-state observables: Zb[q] = sum (-1)^bit |a|^2 ; Xb[q] = sum a_i a_{i^m} ---
    float p[32];
    float tot = 0.f;
    #pragma unroll
    for (int r = 0; r < 32; r++) { p[r] = a[r] * a[r]; tot += p[r]; }

    // wires 0..4 (lane bits)
    #pragma unroll
    for (int q = 0; q < 5; q++) {
      const int m = 1 << (4 - q);
      float z = (lane & m) ? -tot : tot;
      z = wsum(z);
      float xs = 0.f;
      #pragma unroll
      for (int r = 0; r < 32; r++)
        xs = fmaf(a[r], __shfl_xor_sync(FULLM, a[r], m), xs);
      xs = wsum(xs);
      if (lane == 0) { zbs[q] = z; xbs[q] = xs; }
    }
    // wires 5..9 (register bits)
    #pragma unroll
    for (int q = 5; q < 10; q++) {
      const int m = 1 << (9 - q);
      float z = 0.f, xs = 0.f;
      #pragma unroll
      for (int r = 0; r < 32; r++) {
        z += (r & m) ? -p[r] : p[r];
        if ((r & m) == 0) xs = fmaf(a[r], a[r | m], xs);
      }
      z = wsum(z);
      xs = 2.f * wsum(xs);
      if (lane == 0) { zbs[q] = z; xbs[q] = xs; }
    }
  }
  __syncthreads();

  // --- main: out[t][c] = (c<10) ? cos(x)*Zb[c] - sin(x)*Xb[c] : 0 ---
  const int total4 = nTok * 16;  // 64 floats per token = 16 float4
  const float4* __restrict__ x4 = (const float4*)x;
  float4* __restrict__ o4 = (float4*)out;
  for (int idx = blockIdx.x * blockDim.x + threadIdx.x; idx < total4;
       idx += gridDim.x * blockDim.x) {
    const int c4 = idx & 15;
    float4 o = make_float4(0.f, 0.f, 0.f, 0.f);
    if (c4 < 3) {
      const float4 xv = x4[idx];
      const int q0 = c4 * 4;
      float s0, c0, s1, c1;
      sincosf(xv.x, &s0, &c0); o.x = c0 * zbs[q0]     - s0 * xbs[q0];
      sincosf(xv.y, &s1, &c1); o.y = c1 * zbs[q0 + 1] - s1 * xbs[q0 + 1];
      if (c4 < 2) {
        float s2, c2, s3, c3;
        sincosf(xv.z, &s2, &c2); o.z = c2 * zbs[q0 + 2] - s2 * xbs[q0 + 2];
        sincosf(xv.w, &s3, &c3); o.w = c3 * zbs[q0 + 3] - s3 * xbs[q0 + 3];
      }
    }
    o4[idx] = o;
  }
}

extern "C" void kernel_launch(void* const* d_in, const int* in_sizes, int n_in,
                              void* d_out, int out_size) {
  const float* x = (const float*)d_in[0];
  const float* params = (const float*)d_in[1];
  // robust to input ordering: params has exactly NL*NQ = 40 elements
  if (n_in >= 2 && in_sizes[0] == NL * NQ) {
    params = (const float*)d_in[0];
    x = (const float*)d_in[1];
  }
  const int nTok = out_size / 64;  // 64 floats per token row
  hqh_kernel<<<148, 256>>>(x, params, (float*)d_out, nTok);
}

// round 2
// speedup vs baseline: 1.7085x; 1.7085x over previous
#include <cuda_runtime.h>

#define FULLM 0xFFFFFFFFu
#define NQ 10
#define NL 4

// State layout: amplitude index i in [0,1024), wire q <-> bit (9-q) (wire 0 = MSB).
// Thread tid (256 threads) owns amps i = (k<<8)|tid, k in 0..3.
//   k bit1 = i bit9 = wire 0, k bit0 = i bit8 = wire 1  (register-local)
//   tid bits 7..5 = wires 2..4 (cross-warp -> smem exchange)
//   tid bits 4..0 = lane bits  = wires 5..9 (warp shuffle)

__global__ void __launch_bounds__(256)
hqh_kernel(const float* __restrict__ x,
           const float* __restrict__ params,
           float* __restrict__ out,
           int nTok)
{
  __shared__ float buf[2][1024];
  __shared__ float red[8][20];
  __shared__ float zbs[NQ], xbs[NQ];

  const int tid  = threadIdx.x;
  const int lane = tid & 31;
  const int wid  = tid >> 5;

  float a[4];
  int pb = 0;

  #pragma unroll
  for (int l = 0; l < NL; l++) {
    float cs[NQ], sn[NQ];
    #pragma unroll
    for (int q = 0; q < NQ; q++) __sincosf(0.5f * params[l * NQ + q], &sn[q], &cs[q]);

    if (l == 0) {
      // |0...0> -> product state: amp[i] = prod_q (bit_q(i) ? sin : cos)
      float base = 1.f;
      #pragma unroll
      for (int q = 2; q < NQ; q++) base *= ((tid >> (9 - q)) & 1) ? sn[q] : cs[q];
      a[0] = base * cs[0] * cs[1];
      a[1] = base * cs[0] * sn[1];
      a[2] = base * sn[0] * cs[1];
      a[3] = base * sn[0] * sn[1];
    } else {
      // RY wire 0: k-bit1 pairs (0,2),(1,3)
      {
        float l0 = a[0], h0 = a[2], l1 = a[1], h1 = a[3];
        a[0] = cs[0] * l0 - sn[0] * h0;  a[2] = fmaf(sn[0], l0, cs[0] * h0);
        a[1] = cs[0] * l1 - sn[0] * h1;  a[3] = fmaf(sn[0], l1, cs[0] * h1);
      }
      // RY wire 1: k-bit0 pairs (0,1),(2,3)
      {
        float l0 = a[0], h0 = a[1], l1 = a[2], h1 = a[3];
        a[0] = cs[1] * l0 - sn[1] * h0;  a[1] = fmaf(sn[1], l0, cs[1] * h0);
        a[2] = cs[1] * l1 - sn[1] * h1;  a[3] = fmaf(sn[1], l1, cs[1] * h1);
      }
      // RY wires 2..4: smem exchange (double-buffered, 1 BAR each)
      #pragma unroll
      for (int q = 2; q <= 4; q++) {
        const int m = 1 << (9 - q);
        #pragma unroll
        for (int k = 0; k < 4; k++) buf[pb][(k << 8) | tid] = a[k];
        __syncthreads();
        const bool hi = (tid & m) != 0;
        #pragma unroll
        for (int k = 0; k < 4; k++) {
          float p = buf[pb][((k << 8) | tid) ^ m];
          a[k] = hi ? fmaf(sn[q], p, cs[q] * a[k]) : fmaf(-sn[q], p, cs[q] * a[k]);
        }
        pb ^= 1;
      }
      // RY wires 5..9: lane-bit shuffles
      #pragma unroll
      for (int q = 5; q < NQ; q++) {
        const int m = 1 << (9 - q);
        const bool hi = (lane & m) != 0;
        #pragma unroll
        for (int k = 0; k < 4; k++) {
          float p = __shfl_xor_sync(FULLM, a[k], m);
          a[k] = hi ? fmaf(sn[q], p, cs[q] * a[k]) : fmaf(-sn[q], p, cs[q] * a[k]);
        }
      }
    }

    // CNOT ring (0,1)(1,2)...(8,9)(9,0): one composed gather permutation.
    // new[i] = old[sigma_first(...sigma_last(i))]; apply gates to src in reverse order.
    #pragma unroll
    for (int k = 0; k < 4; k++) buf[pb][(k << 8) | tid] = a[k];
    __syncthreads();
    #pragma unroll
    for (int k = 0; k < 4; k++) {
      int src = (k << 8) | tid;
      src ^= ((src >> 0) & 1) << 9;  // (9,0)
      src ^= ((src >> 1) & 1) << 0;  // (8,9)
      src ^= ((src >> 2) & 1) << 1;  // (7,8)
      src ^= ((src >> 3) & 1) << 2;  // (6,7)
      src ^= ((src >> 4) & 1) << 3;  // (5,6)
      src ^= ((src >> 5) & 1) << 4;  // (4,5)
      src ^= ((src >> 6) & 1) << 5;  // (3,4)
      src ^= ((src >> 7) & 1) << 6;  // (2,3)
      src ^= ((src >> 8) & 1) << 7;  // (1,2)
      src ^= ((src >> 9) & 1) << 8;  // (0,1)
      a[k] = buf[pb][src];
    }
    pb ^= 1;
  }

  // ---- observables of the shared base state: Zb[q], Xb[q] ----
  float p4[4];
  #pragma unroll
  for (int k = 0; k < 4; k++) p4[k] = a[k] * a[k];
  const float ptot = p4[0] + p4[1] + p4[2] + p4[3];

  float zc[NQ], xc[NQ];
  // wires 0,1 (local k bits)
  zc[0] = p4[0] + p4[1] - p4[2] - p4[3];
  xc[0] = 2.f * (a[0] * a[2] + a[1] * a[3]);
  zc[1] = p4[0] - p4[1] + p4[2] - p4[3];
  xc[1] = 2.f * (a[0] * a[1] + a[2] * a[3]);

  // store final state for wire 2..4 partner products
  #pragma unroll
  for (int k = 0; k < 4; k++) buf[pb][(k << 8) | tid] = a[k];
  __syncthreads();
  #pragma unroll
  for (int q = 2; q <= 4; q++) {
    const int m = 1 << (9 - q);
    zc[q] = (tid & m) ? -ptot : ptot;
    float s = 0.f;
    #pragma unroll
    for (int k = 0; k < 4; k++) s = fmaf(a[k], buf[pb][((k << 8) | tid) ^ m], s);
    xc[q] = s;
  }
  #pragma unroll
  for (int q = 5; q < NQ; q++) {
    const int m = 1 << (9 - q);
    zc[q] = (lane & m) ? -ptot : ptot;
    float s = 0.f;
    #pragma unroll
    for (int k = 0; k < 4; k++) s = fmaf(a[k], __shfl_xor_sync(FULLM, a[k], m), s);
    xc[q] = s;
  }

  // reduce 20 per-thread partials: warp shfl-reduce -> 8x20 smem -> 20 finishers
  #pragma unroll
  for (int j = 0; j < 20; j++) {
    float v = (j < NQ) ? zc[j] : xc[j - NQ];
    #pragma unroll
    for (int m = 16; m >= 1; m >>= 1) v += __shfl_xor_sync(FULLM, v, m);
    if (lane == 0) red[wid][j] = v;
  }
  __syncthreads();
  if (tid < 20) {
    float s = 0.f;
    #pragma unroll
    for (int w = 0; w < 8; w++) s += red[w][tid];
    if (tid < NQ) zbs[tid] = s; else xbs[tid - NQ] = s;
  }
  __syncthreads();

  // ---- main: out[t][c] = (c<10) ? cos(x)*Zb[c] - sin(x)*Xb[c] : 0 ----
  const int total4 = nTok * 16;  // 64 floats per token = 16 float4
  const float4* __restrict__ x4 = (const float4*)x;
  float4* __restrict__ o4 = (float4*)out;
  for (int idx = blockIdx.x * blockDim.x + threadIdx.x; idx < total4;
       idx += gridDim.x * blockDim.x) {
    const int c4 = idx & 15;
    float4 o = make_float4(0.f, 0.f, 0.f, 0.f);
    if (c4 < 3) {
      const float4 xv = x4[idx];
      const int q0 = c4 * 4;
      float s0, c0, s1, c1;
      __sincosf(xv.x, &s0, &c0); o.x = c0 * zbs[q0]     - s0 * xbs[q0];
      __sincosf(xv.y, &s1, &c1); o.y = c1 * zbs[q0 + 1] - s1 * xbs[q0 + 1];
      if (c4 < 2) {
        float s2, c2, s3, c3;
        __sincosf(xv.z, &s2, &c2); o.z = c2 * zbs[q0 + 2] - s2 * xbs[q0 + 2];
        __sincosf(xv.w, &s3, &c3); o.w = c3 * zbs[q0 + 3] - s3 * xbs[q0 + 3];
      }
    }
    o4[idx] = o;
  }
}

extern "C" void kernel_launch(void* const* d_in, const int* in_sizes, int n_in,
                              void* d_out, int out_size) {
  const float* x = (const float*)d_in[0];
  const float* params = (const float*)d_in[1];
  // robust to input ordering: params has exactly NL*NQ = 40 elements
  if (n_in >= 2 && in_sizes[0] == NL * NQ) {
    params = (const float*)d_in[0];
    x = (const float*)d_in[1];
  }
  const int nTok = out_size / 64;  // 64 floats per token row
  hqh_kernel<<<148, 256>>>(x, params, (float*)d_out, nTok);
}